// round 7
// baseline (speedup 1.0000x reference)
#include <cuda_runtime.h>
#include <cuda_bf16.h>
#include <math.h>
#include <stdint.h>

#define B_ 32
#define T_ 64
#define E_ 256
#define H_ 256
#define P_ 63
#define PB_ 2016
#define NPACK_ 64512
#define PITCH 24   // bf16 elements per smem row in dense kernel (16 data + 8 pad)

#define NCTA_PERS 144
#define NQ_ 18
#define SMEM_A_OFF   196608            // A buffers after 16 chunks * 12288B weights
#define ABUF_STRIDE  8192              // 2 planes * 128 rows * 32B
#define SMEM_TOTAL_PERS (196608 + 3*ABUF_STRIDE)   // 221184

#define DCHUNK 24576                   // dense: A(12288)+B(12288) per buffer
#define SMEM_TOTAL_DENSE (3*DCHUNK)    // 73728

// ------------------------- scratch (device globals) -------------------------
__device__ float g_emb[T_*B_*E_];
__device__ float g_gxa[T_*B_*3*H_];
__device__ float g_gxb[T_*B_*3*H_];
__device__ __nv_bfloat16 g_hhi[2][2][PB_*H_];   // [gru][parity]
__device__ __nv_bfloat16 g_hlo[2][2][PB_*H_];
__device__ __nv_bfloat16 g_whi[2][3*H_*H_];
__device__ __nv_bfloat16 g_wlo[2][3*H_*H_];
__device__ __nv_bfloat16 g_bwhi[E_*H_];
__device__ __nv_bfloat16 g_bwlo[E_*H_];
__device__ __nv_bfloat16 g_mthi[E_*E_];
__device__ __nv_bfloat16 g_mtlo[E_*E_];
__device__ float g_fa[(size_t)NPACK_*H_];
__device__ __nv_bfloat16 g_fbhi[(size_t)NPACK_*H_];
__device__ __nv_bfloat16 g_fblo[(size_t)NPACK_*H_];
__device__ float g_beta[(size_t)NPACK_*E_];
__device__ __nv_bfloat16 g_betahi[(size_t)NPACK_*E_];
__device__ __nv_bfloat16 g_betalo[(size_t)NPACK_*E_];
__device__ float g_ebeta[(size_t)NPACK_*E_];
__device__ float g_pre[P_*T_*B_];
__device__ float g_alpha[P_*T_*B_];
__device__ unsigned g_bar2[2];

// ------------------------- helpers ------------------------------------------
__device__ __forceinline__ uint32_t smem_u32(const void* p) {
    uint32_t a;
    asm("{ .reg .u64 t; cvta.to.shared.u64 t, %1; cvt.u32.u64 %0, t; }" : "=r"(a) : "l"(p));
    return a;
}
__device__ __forceinline__ void ldsm4(uint32_t* r, uint32_t addr) {
    asm volatile("ldmatrix.sync.aligned.m8n8.x4.shared.b16 {%0,%1,%2,%3}, [%4];"
        : "=r"(r[0]), "=r"(r[1]), "=r"(r[2]), "=r"(r[3]) : "r"(addr));
}
__device__ __forceinline__ void mma16816(float* d, const uint32_t* a, const uint32_t* b) {
    asm volatile("mma.sync.aligned.m16n8k16.row.col.f32.bf16.bf16.f32 "
        "{%0,%1,%2,%3}, {%4,%5,%6,%7}, {%8,%9}, {%0,%1,%2,%3};"
        : "+f"(d[0]), "+f"(d[1]), "+f"(d[2]), "+f"(d[3])
        : "r"(a[0]), "r"(a[1]), "r"(a[2]), "r"(a[3]), "r"(b[0]), "r"(b[1]));
}
#define CP_ASYNC16(dst, src) \
    asm volatile("cp.async.cg.shared.global [%0], [%1], 16;" :: "r"(dst), "l"(src))
#define CP_COMMIT() asm volatile("cp.async.commit_group;")
#define CP_WAIT1()  asm volatile("cp.async.wait_group 1;")
#define CP_WAIT0()  asm volatile("cp.async.wait_group 0;")

// ------------------------- prep kernels -------------------------------------
__global__ void zero_planes_kernel() {
    int i = blockIdx.x*256 + threadIdx.x;
    uint32_t* a = (uint32_t*)g_hhi;
    uint32_t* b = (uint32_t*)g_hlo;
    if (i < 2*2*PB_*H_/2) { a[i] = 0u; b[i] = 0u; }
    if (i < 2) g_bar2[i] = 0u;
}
__global__ void prep_w_kernel(const float* __restrict__ wa, const float* __restrict__ wb) {
    int idx = blockIdx.x*256 + threadIdx.x;
    int k = idx & 255;
    int r = (idx >> 8) % 768;
    int gru = idx / (768*256);
    float v = (gru ? wb : wa)[r*256 + k];
    __nv_bfloat16 hi = __float2bfloat16(v);
    g_whi[gru][r*256 + k] = hi;
    g_wlo[gru][r*256 + k] = __float2bfloat16(v - __bfloat162float(hi));
}
__global__ void prep_bw_kernel(const float* __restrict__ bw) {
    int idx = blockIdx.x*256 + threadIdx.x;
    float v = bw[idx];
    __nv_bfloat16 hi = __float2bfloat16(v);
    g_bwhi[idx] = hi;
    g_bwlo[idx] = __float2bfloat16(v - __bfloat162float(hi));
}
__global__ void prep_mt_kernel(const float* __restrict__ emb_w, const float* __restrict__ out_w) {
    int idx = blockIdx.x*256 + threadIdx.x;
    int i = idx >> 8, e = idx & 255;
    float v = out_w[e] * emb_w[e*256 + i];
    __nv_bfloat16 hi = __float2bfloat16(v);
    g_mthi[idx] = hi;
    g_mtlo[idx] = __float2bfloat16(v - __bfloat162float(hi));
}

// ------------------------- fp32 SGEMM (emb / gx) ----------------------------
__device__ __forceinline__ const float* arow_ptr(const float* A, int m, int xmode) {
    if (xmode) { int t = m >> 5, b = m & 31; return A + ((size_t)b*T_ + t)*E_; }
    return A + (size_t)m*E_;
}
__device__ __forceinline__ void sgemm_body(
        const float* A, const float* Bt, const float* bias, float* C,
        int N, int act, int xmode, int m0, int n0) {
    __shared__ float As[2][8][128];
    __shared__ float Bs[2][8][128];
    const int tid = threadIdx.x;
    const int tx = tid & 15, ty = tid >> 4;
    const int lr = tid >> 1;
    const int ks = (tid & 1) * 4;
    const float* pA = arow_ptr(A, m0 + lr, xmode) + ks;
    const float* pB = Bt + (size_t)(n0 + lr) * 256 + ks;
    float acc[2][2][4][4] = {};
    float4 va = *(const float4*)pA;
    float4 vb = *(const float4*)pB;
    {
        const float* f = (const float*)&va;
#pragma unroll
        for (int j = 0; j < 4; j++) As[0][ks+j][lr] = f[j];
        f = (const float*)&vb;
#pragma unroll
        for (int j = 0; j < 4; j++) Bs[0][ks+j][lr] = f[j];
    }
    __syncthreads();
    int buf = 0;
#pragma unroll 1
    for (int c = 0; c < 32; c++) {
        if (c < 31) {
            int off = (c+1)*8;
            va = *(const float4*)(pA + off);
            vb = *(const float4*)(pB + off);
        }
#pragma unroll
        for (int kk = 0; kk < 8; kk++) {
            float4 a0 = *(const float4*)&As[buf][kk][ty*4];
            float4 a1 = *(const float4*)&As[buf][kk][ty*4 + 64];
            float4 b0 = *(const float4*)&Bs[buf][kk][tx*4];
            float4 b1 = *(const float4*)&Bs[buf][kk][tx*4 + 64];
            float aa[2][4] = {{a0.x,a0.y,a0.z,a0.w},{a1.x,a1.y,a1.z,a1.w}};
            float bb[2][4] = {{b0.x,b0.y,b0.z,b0.w},{b1.x,b1.y,b1.z,b1.w}};
#pragma unroll
            for (int rh = 0; rh < 2; rh++)
#pragma unroll
            for (int i = 0; i < 4; i++)
#pragma unroll
            for (int ch = 0; ch < 2; ch++)
#pragma unroll
            for (int j = 0; j < 4; j++)
                acc[rh][ch][i][j] = fmaf(aa[rh][i], bb[ch][j], acc[rh][ch][i][j]);
        }
        if (c < 31) {
            int nb = buf ^ 1;
            const float* f = (const float*)&va;
#pragma unroll
            for (int j = 0; j < 4; j++) As[nb][ks+j][lr] = f[j];
            f = (const float*)&vb;
#pragma unroll
            for (int j = 0; j < 4; j++) Bs[nb][ks+j][lr] = f[j];
            __syncthreads();
            buf = nb;
        }
    }
#pragma unroll
    for (int rh = 0; rh < 2; rh++)
#pragma unroll
    for (int i = 0; i < 4; i++) {
        int m = m0 + rh*64 + ty*4 + i;
#pragma unroll
        for (int ch = 0; ch < 2; ch++) {
            int n = n0 + ch*64 + tx*4;
            float4 v;
            v.x = acc[rh][ch][i][0]; v.y = acc[rh][ch][i][1];
            v.z = acc[rh][ch][i][2]; v.w = acc[rh][ch][i][3];
            if (bias) {
                float4 bz = *(const float4*)&bias[n];
                v.x += bz.x; v.y += bz.y; v.z += bz.z; v.w += bz.w;
            }
            if (act == 1) { v.x = tanhf(v.x); v.y = tanhf(v.y); v.z = tanhf(v.z); v.w = tanhf(v.w); }
            *(float4*)&C[(size_t)m*N + n] = v;
        }
    }
}
__global__ void __launch_bounds__(256, 2)
sgemm128(const float* __restrict__ A, const float* __restrict__ Bt,
         const float* __restrict__ bias, float* __restrict__ C,
         int N, int act, int xmode) {
    sgemm_body(A, Bt, bias, C, N, act, xmode, blockIdx.x*128, blockIdx.y*128);
}
// dual-target gx GEMM: y<6 -> (BtA,biasA,CA); else (BtB,biasB,CB)
__global__ void __launch_bounds__(256, 2)
sgemm128_gx(const float* __restrict__ A,
            const float* __restrict__ BtA, const float* __restrict__ biasA, float* __restrict__ CA,
            const float* __restrict__ BtB, const float* __restrict__ biasB, float* __restrict__ CB) {
    int y = blockIdx.y;
    if (y < 6) sgemm_body(A, BtA, biasA, CA, 3*H_, 0, 0, blockIdx.x*128, y*128);
    else       sgemm_body(A, BtB, biasB, CB, 3*H_, 0, 0, blockIdx.x*128, (y-6)*128);
}

// ------------------------- persistent GRU recurrence ------------------------
// Grid: 144 CTAs x 512 thr. CTA = (gru, cb, q), q in [0,18).
// Weights resident; A streamed via 3-buffer cp.async, 1 sync per chunk.
__global__ void __launch_bounds__(512, 1)
gru_persistent(const float* __restrict__ bhh_a, const float* __restrict__ bhh_b) {
    extern __shared__ __align__(16) unsigned char smem[];
    const int tid = threadIdx.x, lane = tid & 31, wid = tid >> 5;
    const int wm = wid & 3, wn = wid >> 2;
    const int gid = blockIdx.x;
    const int gru = gid & 1, cb = (gid >> 1) & 3, q = gid >> 3;
    const uint32_t sbase = smem_u32(smem);

    // ---- one-time weight slice load ----
    {
        const __nv_bfloat16* Whi = g_whi[gru];
        const __nv_bfloat16* Wlo = g_wlo[gru];
        for (int it = tid; it < 12288; it += 512) {
            int qq = it & 1;
            int r = (it >> 1) % 192;
            int t3 = (it >> 1) / 192;
            int p = t3 & 1;
            int c = t3 >> 1;
            int R = (r >> 6)*256 + cb*64 + (r & 63);
            const __nv_bfloat16* src = (p ? Wlo : Whi) + (size_t)R*256 + c*16 + qq*8;
            *(uint4*)(smem + c*12288 + p*6144 + r*32 + qq*16) = *(const uint4*)src;
        }
    }
    __syncthreads();

    // ---- per-lane ldmatrix offsets ----
    const int a_r = lane & 15, a_c16 = ((lane >> 4) & 1) * 16;
    const int b_r = (lane & 7) + ((lane >> 4) & 1) * 8, b_c16 = (lane & 8) * 2;
    uint32_t abase[3][2][2];   // [buf][plane][i]
#pragma unroll
    for (int bf = 0; bf < 3; bf++)
#pragma unroll
    for (int p = 0; p < 2; p++)
#pragma unroll
    for (int i = 0; i < 2; i++)
        abase[bf][p][i] = sbase + SMEM_A_OFF + bf*ABUF_STRIDE + p*4096u
                        + (uint32_t)((wm*32 + i*16 + a_r)*32 + a_c16);
    uint32_t wboff[2][3];
#pragma unroll
    for (int p = 0; p < 2; p++)
#pragma unroll
    for (int g = 0; g < 3; g++)
        wboff[p][g] = (uint32_t)(p*6144 + (g*64 + wn*16 + b_r)*32 + b_c16);

    const float* bhh = gru ? bhh_b : bhh_a;
    const float* gx  = gru ? g_gxb : g_gxa;
    const int st_q = tid & 1, st_r = (tid >> 1) & 127, st_p = tid >> 8;
    const uint32_t st_dst0 = sbase + SMEM_A_OFF + st_p*4096u + (uint32_t)(st_r*32 + st_q*16);

    const int g8 = lane >> 2, t2 = (lane & 3)*2;
    unsigned* mybar = &g_bar2[gru];

#pragma unroll 1
    for (int step = 0; step < 63; step++) {
        const int par = step & 1;
        const int nch = (63 - step)*2;
        const int c0 = (q*nch)/NQ_, c1 = ((q+1)*nch)/NQ_;
        const int R = (c1 - c0)*16;
        if (R > 0) {
            const __nv_bfloat16* Hhi = g_hhi[gru][par];
            const __nv_bfloat16* Hlo = g_hlo[gru][par];
            const int rowbase = step*32 + c0*16;
            const int ng = R >> 4;
            const bool st_on = (st_r < R);
            const __nv_bfloat16* st_src = (st_p ? Hlo : Hhi)
                + (size_t)(rowbase + (st_on ? st_r : 0))*H_ + st_q*8;

            float acc[3][2][2][4] = {};
            if (st_on) CP_ASYNC16(st_dst0, st_src);
            CP_COMMIT();
            if (st_on) CP_ASYNC16(st_dst0 + ABUF_STRIDE, st_src + 16);
            CP_COMMIT();
            int bufi = 0;
#pragma unroll 1
            for (int c = 0; c < 16; c++) {
                if (c < 15) { CP_WAIT1(); } else { CP_WAIT0(); }
                __syncthreads();
                if (c < 14) {
                    int nb = bufi + 2; if (nb >= 3) nb -= 3;
                    if (st_on) CP_ASYNC16(st_dst0 + (uint32_t)(nb*ABUF_STRIDE), st_src + (c+2)*16);
                    CP_COMMIT();
                }
                if (2*wm < ng) {
                    const bool two = (2*wm + 1 < ng);
                    uint32_t Ah[2][4], Al[2][4];
                    ldsm4(Ah[0], abase[bufi][0][0]);
                    ldsm4(Al[0], abase[bufi][1][0]);
                    if (two) { ldsm4(Ah[1], abase[bufi][0][1]); ldsm4(Al[1], abase[bufi][1][1]); }
                    const uint32_t wbc = sbase + (uint32_t)(c*12288);
#pragma unroll
                    for (int g = 0; g < 3; g++) {
                        uint32_t Bh[4], Bl[4];
                        ldsm4(Bh, wbc + wboff[0][g]);
                        ldsm4(Bl, wbc + wboff[1][g]);
#pragma unroll
                        for (int j = 0; j < 2; j++) {
                            mma16816(acc[g][0][j], Ah[0], &Bh[j*2]);
                            mma16816(acc[g][0][j], Ah[0], &Bl[j*2]);
                            mma16816(acc[g][0][j], Al[0], &Bh[j*2]);
                        }
                        if (two) {
#pragma unroll
                            for (int j = 0; j < 2; j++) {
                                mma16816(acc[g][1][j], Ah[1], &Bh[j*2]);
                                mma16816(acc[g][1][j], Ah[1], &Bl[j*2]);
                                mma16816(acc[g][1][j], Al[1], &Bh[j*2]);
                            }
                        }
                    }
                }
                bufi++; if (bufi == 3) bufi = 0;
            }
            // ---- epilogue ----
            __nv_bfloat16* Hhi_n = g_hhi[gru][par^1];
            __nv_bfloat16* Hlo_n = g_hlo[gru][par^1];
            const size_t offk = (size_t)32*(63*step - (step*(step-1))/2);
#pragma unroll
            for (int i = 0; i < 2; i++) {
                if (2*wm + i >= ng) continue;
#pragma unroll
                for (int half = 0; half < 2; half++) {
                    int grow = rowbase + wm*32 + i*16 + g8 + half*8;
                    int gxrow = grow - step*32;
                    const float* gxr = gx + (size_t)gxrow*(3*H_);
                    size_t prow = offk + gxrow;
#pragma unroll
                    for (int j = 0; j < 2; j++) {
                        int cc = cb*64 + wn*16 + j*8 + t2;
                        float2 gx_r = *(const float2*)&gxr[cc];
                        float2 gx_z = *(const float2*)&gxr[H_ + cc];
                        float2 gx_n = *(const float2*)&gxr[2*H_ + cc];
                        float2 bh_r = *(const float2*)&bhh[cc];
                        float2 bh_z = *(const float2*)&bhh[H_ + cc];
                        float2 bh_n = *(const float2*)&bhh[2*H_ + cc];
                        __nv_bfloat162 ho_hi = *(const __nv_bfloat162*)&Hhi[(size_t)grow*H_ + cc];
                        __nv_bfloat162 ho_lo = *(const __nv_bfloat162*)&Hlo[(size_t)grow*H_ + cc];
                        float hn2[2];
#pragma unroll
                        for (int u = 0; u < 2; u++) {
                            int ai = half*2 + u;
                            float rp = acc[0][i][j][ai] + (u ? bh_r.y : bh_r.x) + (u ? gx_r.y : gx_r.x);
                            float zp = acc[1][i][j][ai] + (u ? bh_z.y : bh_z.x) + (u ? gx_z.y : gx_z.x);
                            float np = acc[2][i][j][ai] + (u ? bh_n.y : bh_n.x);
                            float r = 1.f/(1.f + expf(-rp));
                            float z = 1.f/(1.f + expf(-zp));
                            float n = tanhf((u ? gx_n.y : gx_n.x) + r*np);
                            float hold = __bfloat162float(u ? ho_hi.y : ho_hi.x)
                                       + __bfloat162float(u ? ho_lo.y : ho_lo.x);
                            hn2[u] = (1.f - z)*n + z*hold;
                        }
                        __nv_bfloat162 hi2, lo2;
                        hi2.x = __float2bfloat16(hn2[0]); hi2.y = __float2bfloat16(hn2[1]);
                        lo2.x = __float2bfloat16(hn2[0] - __bfloat162float(hi2.x));
                        lo2.y = __float2bfloat16(hn2[1] - __bfloat162float(hi2.y));
                        *(__nv_bfloat162*)&Hhi_n[(size_t)grow*H_ + cc] = hi2;
                        *(__nv_bfloat162*)&Hlo_n[(size_t)grow*H_ + cc] = lo2;
                        if (gru == 0) {
                            float2 f2; f2.x = 0.5f*hn2[0]; f2.y = 0.5f*hn2[1];
                            *(float2*)&g_fa[prow*H_ + cc] = f2;
                        } else {
                            float f0 = 0.5f*hn2[0], f1 = 0.5f*hn2[1];
                            __nv_bfloat162 fh, fl;
                            fh.x = __float2bfloat16(f0); fh.y = __float2bfloat16(f1);
                            fl.x = __float2bfloat16(f0 - __bfloat162float(fh.x));
                            fl.y = __float2bfloat16(f1 - __bfloat162float(fh.y));
                            *(__nv_bfloat162*)&g_fbhi[prow*H_ + cc] = fh;
                            *(__nv_bfloat162*)&g_fblo[prow*H_ + cc] = fl;
                        }
                    }
                }
            }
        }
        // ---- per-gru grid barrier (72 CTAs each) ----
        __syncthreads();
        if (tid == 0) {
            __threadfence();
            atomicAdd(mybar, 1u);
            const unsigned target = 72u*(unsigned)(step+1);
            unsigned v;
            do {
                asm volatile("ld.acquire.gpu.u32 %0, [%1];" : "=r"(v) : "l"(mybar));
            } while (v < target);
        }
        __syncthreads();
    }
}

// ------------------------- mma dense GEMM (M x 256, K=256) ------------------
// 3-buffer cp.async pipeline, 1 sync per chunk.
__global__ void __launch_bounds__(512, 1)
dense_mma(const __nv_bfloat16* __restrict__ Ahi, const __nv_bfloat16* __restrict__ Alo,
          const __nv_bfloat16* __restrict__ Bthi, const __nv_bfloat16* __restrict__ Btlo,
          const float* __restrict__ bias, int act, float* __restrict__ outf,
          __nv_bfloat16* __restrict__ Phi, __nv_bfloat16* __restrict__ Plo) {
    extern __shared__ __align__(16) unsigned char smem[];
    const int tid = threadIdx.x, lane = tid & 31, wid = tid >> 5;
    const int wm = wid & 3, wn = wid >> 2;
    const int cb = blockIdx.y;
    const int rowbase = blockIdx.x * 128;
    const uint32_t sbase = smem_u32(smem);

    float acc[2][4][4] = {};

    const int a_r = lane & 15, a_c16 = ((lane >> 4) & 1) * 16;
    const int b_r = (lane & 7) + ((lane >> 4) & 1) * 8, b_c16 = (lane & 8) * 2;
    uint32_t aoff[3][2][2], boff[3][2][2];
#pragma unroll
    for (int bf = 0; bf < 3; bf++)
#pragma unroll
    for (int p = 0; p < 2; p++) {
#pragma unroll
        for (int i = 0; i < 2; i++)
            aoff[bf][p][i] = sbase + bf*DCHUNK + p*6144u
                           + (uint32_t)((wm*32 + i*16 + a_r)*48 + a_c16);
#pragma unroll
        for (int h2 = 0; h2 < 2; h2++)
            boff[bf][p][h2] = sbase + bf*DCHUNK + 12288u + p*6144u
                           + (uint32_t)((wn*32 + h2*16 + b_r)*48 + b_c16);
    }

    const int st_q = tid & 1, st_r = (tid >> 1) & 127, st_p = tid >> 8;
    const uint32_t stA = sbase + st_p*6144u + (uint32_t)(st_r*48 + st_q*16);
    const uint32_t stB = stA + 12288u;
    const __nv_bfloat16* srcA = (st_p ? Alo : Ahi) + (size_t)(rowbase + st_r)*256 + st_q*8;
    const __nv_bfloat16* srcB = (st_p ? Btlo : Bthi) + (size_t)(cb*128 + st_r)*256 + st_q*8;

    CP_ASYNC16(stA, srcA); CP_ASYNC16(stB, srcB); CP_COMMIT();
    CP_ASYNC16(stA + DCHUNK, srcA + 16); CP_ASYNC16(stB + DCHUNK, srcB + 16); CP_COMMIT();

    int bufi = 0;
#pragma unroll 1
    for (int c = 0; c < 16; c++) {
        if (c < 15) { CP_WAIT1(); } else { CP_WAIT0(); }
        __syncthreads();
        if (c < 14) {
            int nb = bufi + 2; if (nb >= 3) nb -= 3;
            CP_ASYNC16(stA + (uint32_t)(nb*DCHUNK), srcA + (c+2)*16);
            CP_ASYNC16(stB + (uint32_t)(nb*DCHUNK), srcB + (c+2)*16);
            CP_COMMIT();
        }
        uint32_t Ah[2][4], Al[2][4], Bh[8], Bl[8];
        ldsm4(Ah[0], aoff[bufi][0][0]); ldsm4(Ah[1], aoff[bufi][0][1]);
        ldsm4(Al[0], aoff[bufi][1][0]); ldsm4(Al[1], aoff[bufi][1][1]);
        ldsm4(Bh,   boff[bufi][0][0]); ldsm4(Bh+4, boff[bufi][0][1]);
        ldsm4(Bl,   boff[bufi][1][0]); ldsm4(Bl+4, boff[bufi][1][1]);
#pragma unroll
        for (int i = 0; i < 2; i++)
#pragma unroll
        for (int j = 0; j < 4; j++) {
            mma16816(acc[i][j], Ah[i], &Bh[j*2]);
            mma16816(acc[i][j], Ah[i], &Bl[j*2]);
            mma16816(acc[i][j], Al[i], &Bh[j*2]);
        }
        bufi++; if (bufi == 3) bufi = 0;
    }

    const int g8 = lane >> 2, t2 = (lane & 3)*2;
#pragma unroll
    for (int i = 0; i < 2; i++)
#pragma unroll
    for (int half = 0; half < 2; half++) {
        int grow = rowbase + wm*32 + i*16 + g8 + half*8;
#pragma unroll
        for (int j = 0; j < 4; j++) {
            int cc = cb*128 + wn*32 + j*8 + t2;
            float v0 = acc[i][j][half*2 + 0];
            float v1 = acc[i][j][half*2 + 1];
            if (bias) { v0 += bias[cc]; v1 += bias[cc+1]; }
            if (act == 1) { v0 = tanhf(v0); v1 = tanhf(v1); }
            float2 f2; f2.x = v0; f2.y = v1;
            *(float2*)&outf[(size_t)grow*E_ + cc] = f2;
            if (Phi) {
                __nv_bfloat162 hi2, lo2;
                hi2.x = __float2bfloat16(v0); hi2.y = __float2bfloat16(v1);
                lo2.x = __float2bfloat16(v0 - __bfloat162float(hi2.x));
                lo2.y = __float2bfloat16(v1 - __bfloat162float(hi2.y));
                *(__nv_bfloat162*)&Phi[(size_t)grow*E_ + cc] = hi2;
                *(__nv_bfloat162*)&Plo[(size_t)grow*E_ + cc] = lo2;
            }
        }
    }
}

// ------------------------- pre / alpha / reduce -----------------------------
__global__ void pre_kernel(const float* __restrict__ alpha_w,
                           const float* __restrict__ alpha_b) {
    int gw = (blockIdx.x*blockDim.x + threadIdx.x) >> 5;
    int lane = threadIdx.x & 31;
    if (gw >= NPACK_) return;
    int k = 0, off = 0;
    while (k < 62 && off + (63-k)*32 <= gw) { off += (63-k)*32; k++; }
    int l = gw - off;
    int t = l >> 5, b = l & 31;
    int p = k + t;
    const float* fa = g_fa + (size_t)gw*H_;
    float s = 0.f;
    for (int e = lane; e < H_; e += 32) s += fa[e]*alpha_w[e];
#pragma unroll
    for (int o=16;o;o>>=1) s += __shfl_xor_sync(0xffffffffu, s, o);
    if (lane == 0) g_pre[(p*T_ + t)*B_ + b] = s + alpha_b[0];
}

__global__ void alpha_kernel() {
    int gw = (blockIdx.x*blockDim.x + threadIdx.x) >> 5;
    int lane = threadIdx.x & 31;
    if (gw >= PB_) return;
    int p = gw >> 5, b = gw & 31;
    float v0 = (lane      <= p) ? g_pre[(p*T_+lane   )*B_+b] : -1e30f;
    float v1 = (lane + 32 <= p) ? g_pre[(p*T_+lane+32)*B_+b] : -1e30f;
    float m = fmaxf(v0, v1);
#pragma unroll
    for (int o=16;o;o>>=1) m = fmaxf(m, __shfl_xor_sync(0xffffffffu, m, o));
    float e0 = (lane      <= p) ? expf(v0-m) : 0.f;
    float e1 = (lane + 32 <= p) ? expf(v1-m) : 0.f;
    float s = e0 + e1;
#pragma unroll
    for (int o=16;o;o>>=1) s += __shfl_xor_sync(0xffffffffu, s, o);
    float inv = 1.f/s;
    g_alpha[(p*T_+lane   )*B_+b] = e0*inv;
    g_alpha[(p*T_+lane+32)*B_+b] = e1*inv;
}

__global__ void reduce_kernel(const float* __restrict__ x,
                              const float* __restrict__ out_w,
                              const float* __restrict__ out_b,
                              float* __restrict__ out) {
    int pb = blockIdx.x;
    int p = 62 - (pb >> 5);        // largest prefixes first (tail balance)
    int b = pb & 31;
    int e = threadIdx.x;
    float cc = 0.f, gg = 0.f;
    for (int t = 0; t <= p; t++) {
        float a = g_alpha[(p*T_+t)*B_+b];
        int kk = p - t;
        int offk = 32*(63*kk - (kk*(kk-1))/2);
        size_t prow = (size_t)offk + t*32 + b;
        cc += a * g_beta [prow*E_ + e] * g_emb[((size_t)(t*B_+b))*E_ + e];
        gg += a * g_ebeta[prow*E_ + e] * x[((size_t)b*T_ + t)*E_ + e];
    }
    out[B_*P_ + ((size_t)(b*P_+p))*E_ + e] = gg / (float)(p+1);
    __shared__ float red[256];
    red[e] = cc * out_w[e];
    __syncthreads();
    for (int s2=128; s2; s2>>=1) { if (e < s2) red[e] += red[e+s2]; __syncthreads(); }
    if (e == 0) out[b*P_ + p] = red[0] + out_b[0];
}

// ------------------------- launch -------------------------------------------
extern "C" void kernel_launch(void* const* d_in, const int* in_sizes, int n_in,
                              void* d_out, int out_size) {
    (void)in_sizes; (void)n_in; (void)out_size;
    const float* x       = (const float*)d_in[0];
    const float* emb_w   = (const float*)d_in[1];
    const float* emb_b   = (const float*)d_in[2];
    const float* a_wih   = (const float*)d_in[3];
    const float* a_whh   = (const float*)d_in[4];
    const float* a_bih   = (const float*)d_in[5];
    const float* a_bhh   = (const float*)d_in[6];
    const float* b_wih   = (const float*)d_in[7];
    const float* b_whh   = (const float*)d_in[8];
    const float* b_bih   = (const float*)d_in[9];
    const float* b_bhh   = (const float*)d_in[10];
    const float* alpha_w = (const float*)d_in[11];
    const float* alpha_b = (const float*)d_in[12];
    const float* beta_w  = (const float*)d_in[13];
    const float* beta_b  = (const float*)d_in[14];
    const float* out_w   = (const float*)d_in[15];
    const float* out_b   = (const float*)d_in[16];
    float* out = (float*)d_out;

    cudaFuncSetAttribute(gru_persistent, cudaFuncAttributeMaxDynamicSharedMemorySize, SMEM_TOTAL_PERS);
    cudaFuncSetAttribute(dense_mma,      cudaFuncAttributeMaxDynamicSharedMemorySize, SMEM_TOTAL_DENSE);

    float *p_emb=0, *p_gxa=0, *p_gxb=0, *p_beta=0, *p_ebeta=0;
    __nv_bfloat16 *p_fbhi=0, *p_fblo=0, *p_bwhi=0, *p_bwlo=0;
    __nv_bfloat16 *p_mthi=0, *p_mtlo=0, *p_bhi=0, *p_blo=0;
    cudaGetSymbolAddress((void**)&p_emb,   g_emb);
    cudaGetSymbolAddress((void**)&p_gxa,   g_gxa);
    cudaGetSymbolAddress((void**)&p_gxb,   g_gxb);
    cudaGetSymbolAddress((void**)&p_beta,  g_beta);
    cudaGetSymbolAddress((void**)&p_ebeta, g_ebeta);
    cudaGetSymbolAddress((void**)&p_fbhi,  g_fbhi);
    cudaGetSymbolAddress((void**)&p_fblo,  g_fblo);
    cudaGetSymbolAddress((void**)&p_bwhi,  g_bwhi);
    cudaGetSymbolAddress((void**)&p_bwlo,  g_bwlo);
    cudaGetSymbolAddress((void**)&p_mthi,  g_mthi);
    cudaGetSymbolAddress((void**)&p_mtlo,  g_mtlo);
    cudaGetSymbolAddress((void**)&p_bhi,   g_betahi);
    cudaGetSymbolAddress((void**)&p_blo,   g_betalo);

    zero_planes_kernel<<<(2*2*PB_*H_/2 + 255)/256, 256>>>();
    prep_w_kernel<<<(2*768*256)/256, 256>>>(a_whh, b_whh);
    prep_bw_kernel<<<256, 256>>>(beta_w);
    prep_mt_kernel<<<256, 256>>>(emb_w, out_w);

    sgemm128<<<dim3((T_*B_)/128, E_/128), 256>>>(x, emb_w, emb_b, p_emb, E_, 0, 1);
    sgemm128_gx<<<dim3((T_*B_)/128, 12), 256>>>(p_emb, a_wih, a_bih, p_gxa,
                                                b_wih, b_bih, p_gxb);

    gru_persistent<<<NCTA_PERS, 512, SMEM_TOTAL_PERS>>>(a_bhh, b_bhh);

    pre_kernel<<<(NPACK_*32 + 255)/256, 256>>>(alpha_w, alpha_b);
    alpha_kernel<<<(PB_*32 + 255)/256, 256>>>();

    dense_mma<<<dim3(NPACK_/128, 2), 512, SMEM_TOTAL_DENSE>>>(
        p_fbhi, p_fblo, p_bwhi, p_bwlo, beta_b, 1, p_beta, p_bhi, p_blo);
    dense_mma<<<dim3(NPACK_/128, 2), 512, SMEM_TOTAL_DENSE>>>(
        p_bhi, p_blo, p_mthi, p_mtlo, (const float*)0, 0, p_ebeta,
        (__nv_bfloat16*)0, (__nv_bfloat16*)0);

    reduce_kernel<<<PB_, 256>>>(x, out_w, out_b, out);
}

// round 8
// speedup vs baseline: 1.0498x; 1.0498x over previous
#include <cuda_runtime.h>
#include <cuda_bf16.h>
#include <math.h>
#include <stdint.h>

#define B_ 32
#define T_ 64
#define E_ 256
#define H_ 256
#define P_ 63
#define PB_ 2016
#define NPACK_ 64512
#define PITCH 24   // bf16 elements per smem row (16 data + 8 pad) = 48B

#define NCTA_PERS 144
#define NQ_ 18
#define SMEM_A_OFF   196608            // A buffers after 16 chunks * 12288B weights
#define ABUF_STRIDE  12288             // 2 planes * 128 rows * 48B
#define SMEM_TOTAL_PERS (196608 + 2*ABUF_STRIDE)   // 221184

#define DCHUNK 24576                   // dense: A(12288)+B(12288) per buffer
#define SMEM_TOTAL_DENSE (3*DCHUNK)    // 73728

// ------------------------- scratch (device globals) -------------------------
__device__ float g_emb[T_*B_*E_];
__device__ float g_gxa[T_*B_*3*H_];
__device__ float g_gxb[T_*B_*3*H_];
__device__ __nv_bfloat16 g_hhi[2][2][PB_*H_];   // [gru][parity]
__device__ __nv_bfloat16 g_hlo[2][2][PB_*H_];
__device__ __nv_bfloat16 g_whi[2][3*H_*H_];
__device__ __nv_bfloat16 g_wlo[2][3*H_*H_];
__device__ __nv_bfloat16 g_bwhi[E_*H_];
__device__ __nv_bfloat16 g_bwlo[E_*H_];
__device__ __nv_bfloat16 g_mthi[E_*E_];
__device__ __nv_bfloat16 g_mtlo[E_*E_];
__device__ float g_prep[(size_t)NPACK_*16];     // pre partials [prow][cb*4+wn]
__device__ __nv_bfloat16 g_fbhi[(size_t)NPACK_*H_];
__device__ __nv_bfloat16 g_fblo[(size_t)NPACK_*H_];
__device__ float g_beta[(size_t)NPACK_*E_];
__device__ __nv_bfloat16 g_betahi[(size_t)NPACK_*E_];
__device__ __nv_bfloat16 g_betalo[(size_t)NPACK_*E_];
__device__ float g_ebeta[(size_t)NPACK_*E_];
__device__ float g_alpha[P_*T_*B_];
__device__ unsigned g_bar2[2];

// ------------------------- helpers ------------------------------------------
__device__ __forceinline__ uint32_t smem_u32(const void* p) {
    uint32_t a;
    asm("{ .reg .u64 t; cvta.to.shared.u64 t, %1; cvt.u32.u64 %0, t; }" : "=r"(a) : "l"(p));
    return a;
}
__device__ __forceinline__ void ldsm4(uint32_t* r, uint32_t addr) {
    asm volatile("ldmatrix.sync.aligned.m8n8.x4.shared.b16 {%0,%1,%2,%3}, [%4];"
        : "=r"(r[0]), "=r"(r[1]), "=r"(r[2]), "=r"(r[3]) : "r"(addr));
}
__device__ __forceinline__ void mma16816(float* d, const uint32_t* a, const uint32_t* b) {
    asm volatile("mma.sync.aligned.m16n8k16.row.col.f32.bf16.bf16.f32 "
        "{%0,%1,%2,%3}, {%4,%5,%6,%7}, {%8,%9}, {%0,%1,%2,%3};"
        : "+f"(d[0]), "+f"(d[1]), "+f"(d[2]), "+f"(d[3])
        : "r"(a[0]), "r"(a[1]), "r"(a[2]), "r"(a[3]), "r"(b[0]), "r"(b[1]));
}
#define CP_ASYNC16(dst, src) \
    asm volatile("cp.async.cg.shared.global [%0], [%1], 16;" :: "r"(dst), "l"(src))
#define CP_COMMIT() asm volatile("cp.async.commit_group;")
#define CP_WAIT1()  asm volatile("cp.async.wait_group 1;")
#define CP_WAIT0()  asm volatile("cp.async.wait_group 0;")

// ------------------------- prep kernels -------------------------------------
__global__ void zero_planes_kernel() {
    int i = blockIdx.x*256 + threadIdx.x;
    uint32_t* a = (uint32_t*)g_hhi;
    uint32_t* b = (uint32_t*)g_hlo;
    if (i < 2*2*PB_*H_/2) { a[i] = 0u; b[i] = 0u; }
    if (i < 2) g_bar2[i] = 0u;
}
__global__ void prep_w_kernel(const float* __restrict__ wa, const float* __restrict__ wb) {
    int idx = blockIdx.x*256 + threadIdx.x;
    int k = idx & 255;
    int r = (idx >> 8) % 768;
    int gru = idx / (768*256);
    float v = (gru ? wb : wa)[r*256 + k];
    __nv_bfloat16 hi = __float2bfloat16(v);
    g_whi[gru][r*256 + k] = hi;
    g_wlo[gru][r*256 + k] = __float2bfloat16(v - __bfloat162float(hi));
}
__global__ void prep_bw_kernel(const float* __restrict__ bw) {
    int idx = blockIdx.x*256 + threadIdx.x;
    float v = bw[idx];
    __nv_bfloat16 hi = __float2bfloat16(v);
    g_bwhi[idx] = hi;
    g_bwlo[idx] = __float2bfloat16(v - __bfloat162float(hi));
}
__global__ void prep_mt_kernel(const float* __restrict__ emb_w, const float* __restrict__ out_w) {
    int idx = blockIdx.x*256 + threadIdx.x;
    int i = idx >> 8, e = idx & 255;
    float v = out_w[e] * emb_w[e*256 + i];
    __nv_bfloat16 hi = __float2bfloat16(v);
    g_mthi[idx] = hi;
    g_mtlo[idx] = __float2bfloat16(v - __bfloat162float(hi));
}

// ------------------------- fp32 SGEMM (emb / gx) ----------------------------
__device__ __forceinline__ const float* arow_ptr(const float* A, int m, int xmode) {
    if (xmode) { int t = m >> 5, b = m & 31; return A + ((size_t)b*T_ + t)*E_; }
    return A + (size_t)m*E_;
}
__device__ __forceinline__ void sgemm_body(
        const float* A, const float* Bt, const float* bias, float* C,
        int N, int act, int xmode, int m0, int n0) {
    __shared__ float As[2][8][128];
    __shared__ float Bs[2][8][128];
    const int tid = threadIdx.x;
    const int tx = tid & 15, ty = tid >> 4;
    const int lr = tid >> 1;
    const int ks = (tid & 1) * 4;
    const float* pA = arow_ptr(A, m0 + lr, xmode) + ks;
    const float* pB = Bt + (size_t)(n0 + lr) * 256 + ks;
    float acc[2][2][4][4] = {};
    float4 va = *(const float4*)pA;
    float4 vb = *(const float4*)pB;
    {
        const float* f = (const float*)&va;
#pragma unroll
        for (int j = 0; j < 4; j++) As[0][ks+j][lr] = f[j];
        f = (const float*)&vb;
#pragma unroll
        for (int j = 0; j < 4; j++) Bs[0][ks+j][lr] = f[j];
    }
    __syncthreads();
    int buf = 0;
#pragma unroll 1
    for (int c = 0; c < 32; c++) {
        if (c < 31) {
            int off = (c+1)*8;
            va = *(const float4*)(pA + off);
            vb = *(const float4*)(pB + off);
        }
#pragma unroll
        for (int kk = 0; kk < 8; kk++) {
            float4 a0 = *(const float4*)&As[buf][kk][ty*4];
            float4 a1 = *(const float4*)&As[buf][kk][ty*4 + 64];
            float4 b0 = *(const float4*)&Bs[buf][kk][tx*4];
            float4 b1 = *(const float4*)&Bs[buf][kk][tx*4 + 64];
            float aa[2][4] = {{a0.x,a0.y,a0.z,a0.w},{a1.x,a1.y,a1.z,a1.w}};
            float bb[2][4] = {{b0.x,b0.y,b0.z,b0.w},{b1.x,b1.y,b1.z,b1.w}};
#pragma unroll
            for (int rh = 0; rh < 2; rh++)
#pragma unroll
            for (int i = 0; i < 4; i++)
#pragma unroll
            for (int ch = 0; ch < 2; ch++)
#pragma unroll
            for (int j = 0; j < 4; j++)
                acc[rh][ch][i][j] = fmaf(aa[rh][i], bb[ch][j], acc[rh][ch][i][j]);
        }
        if (c < 31) {
            int nb = buf ^ 1;
            const float* f = (const float*)&va;
#pragma unroll
            for (int j = 0; j < 4; j++) As[nb][ks+j][lr] = f[j];
            f = (const float*)&vb;
#pragma unroll
            for (int j = 0; j < 4; j++) Bs[nb][ks+j][lr] = f[j];
            __syncthreads();
            buf = nb;
        }
    }
#pragma unroll
    for (int rh = 0; rh < 2; rh++)
#pragma unroll
    for (int i = 0; i < 4; i++) {
        int m = m0 + rh*64 + ty*4 + i;
#pragma unroll
        for (int ch = 0; ch < 2; ch++) {
            int n = n0 + ch*64 + tx*4;
            float4 v;
            v.x = acc[rh][ch][i][0]; v.y = acc[rh][ch][i][1];
            v.z = acc[rh][ch][i][2]; v.w = acc[rh][ch][i][3];
            if (bias) {
                float4 bz = *(const float4*)&bias[n];
                v.x += bz.x; v.y += bz.y; v.z += bz.z; v.w += bz.w;
            }
            if (act == 1) { v.x = tanhf(v.x); v.y = tanhf(v.y); v.z = tanhf(v.z); v.w = tanhf(v.w); }
            *(float4*)&C[(size_t)m*N + n] = v;
        }
    }
}
__global__ void __launch_bounds__(256, 2)
sgemm128(const float* __restrict__ A, const float* __restrict__ Bt,
         const float* __restrict__ bias, float* __restrict__ C,
         int N, int act, int xmode) {
    sgemm_body(A, Bt, bias, C, N, act, xmode, blockIdx.x*128, blockIdx.y*128);
}
__global__ void __launch_bounds__(256, 2)
sgemm128_gx(const float* __restrict__ A,
            const float* __restrict__ BtA, const float* __restrict__ biasA, float* __restrict__ CA,
            const float* __restrict__ BtB, const float* __restrict__ biasB, float* __restrict__ CB) {
    int y = blockIdx.y;
    if (y < 6) sgemm_body(A, BtA, biasA, CA, 3*H_, 0, 0, blockIdx.x*128, y*128);
    else       sgemm_body(A, BtB, biasB, CB, 3*H_, 0, 0, blockIdx.x*128, (y-6)*128);
}

// ------------------------- persistent GRU recurrence ------------------------
// Grid: 144 CTAs x 512 thr. CTA = (gru, cb, q), q in [0,18).
// Weights resident; A via 2-buffer cp.async, ONE sync per chunk, 48B pitch.
__global__ void __launch_bounds__(512, 1)
gru_persistent(const float* __restrict__ bhh_a, const float* __restrict__ bhh_b,
               const float* __restrict__ alpha_w) {
    extern __shared__ __align__(16) unsigned char smem[];
    const int tid = threadIdx.x, lane = tid & 31, wid = tid >> 5;
    const int wm = wid & 3, wn = wid >> 2;
    const int gid = blockIdx.x;
    const int gru = gid & 1, cb = (gid >> 1) & 3, q = gid >> 3;
    const uint32_t sbase = smem_u32(smem);

    // ---- one-time weight slice load ----
    {
        const __nv_bfloat16* Whi = g_whi[gru];
        const __nv_bfloat16* Wlo = g_wlo[gru];
        for (int it = tid; it < 12288; it += 512) {
            int qq = it & 1;
            int r = (it >> 1) % 192;
            int t3 = (it >> 1) / 192;
            int p = t3 & 1;
            int c = t3 >> 1;
            int R = (r >> 6)*256 + cb*64 + (r & 63);
            const __nv_bfloat16* src = (p ? Wlo : Whi) + (size_t)R*256 + c*16 + qq*8;
            *(uint4*)(smem + c*12288 + p*6144 + r*32 + qq*16) = *(const uint4*)src;
        }
    }
    __syncthreads();

    // ---- per-lane ldmatrix offsets (48B A pitch: conflict-free) ----
    const int a_r = lane & 15, a_c16 = ((lane >> 4) & 1) * 16;
    const int b_r = (lane & 7) + ((lane >> 4) & 1) * 8, b_c16 = (lane & 8) * 2;
    uint32_t abase[2][2][2];   // [buf][plane][i]
#pragma unroll
    for (int bf = 0; bf < 2; bf++)
#pragma unroll
    for (int p = 0; p < 2; p++)
#pragma unroll
    for (int i = 0; i < 2; i++)
        abase[bf][p][i] = sbase + SMEM_A_OFF + bf*ABUF_STRIDE + p*6144u
                        + (uint32_t)((wm*32 + i*16 + a_r)*48 + a_c16);
    uint32_t wboff[2][3];
#pragma unroll
    for (int p = 0; p < 2; p++)
#pragma unroll
    for (int g = 0; g < 3; g++)
        wboff[p][g] = (uint32_t)(p*6144 + (g*64 + wn*16 + b_r)*32 + b_c16);

    const float* bhh = gru ? bhh_b : bhh_a;
    const float* gx  = gru ? g_gxb : g_gxa;
    const int st_q = tid & 1, st_r = (tid >> 1) & 127, st_p = tid >> 8;
    const uint32_t st_dst0 = sbase + SMEM_A_OFF + st_p*6144u + (uint32_t)(st_r*48 + st_q*16);

    const int g8 = lane >> 2, t2 = (lane & 3)*2;
    unsigned* mybar = &g_bar2[gru];

#pragma unroll 1
    for (int step = 0; step < 63; step++) {
        const int par = step & 1;
        const int nch = (63 - step)*2;
        const int c0 = (q*nch)/NQ_, c1 = ((q+1)*nch)/NQ_;
        const int R = (c1 - c0)*16;
        if (R > 0) {
            const __nv_bfloat16* Hhi = g_hhi[gru][par];
            const __nv_bfloat16* Hlo = g_hlo[gru][par];
            const int rowbase = step*32 + c0*16;
            const int ng = R >> 4;
            const bool st_on = (st_r < R);
            const __nv_bfloat16* st_src = (st_p ? Hlo : Hhi)
                + (size_t)(rowbase + (st_on ? st_r : 0))*H_ + st_q*8;

            float acc[3][2][2][4] = {};
            if (st_on) CP_ASYNC16(st_dst0, st_src);
            CP_COMMIT();
#pragma unroll 1
            for (int c = 0; c < 16; c++) {
                CP_WAIT0();
                __syncthreads();
                if (c < 15) {
                    if (st_on) CP_ASYNC16(st_dst0 + (uint32_t)(((c+1)&1)*ABUF_STRIDE),
                                          st_src + (c+1)*16);
                    CP_COMMIT();
                }
                const int bufi = c & 1;
                if (2*wm < ng) {
                    const bool two = (2*wm + 1 < ng);
                    uint32_t Ah[2][4], Al[2][4];
                    ldsm4(Ah[0], abase[bufi][0][0]);
                    ldsm4(Al[0], abase[bufi][1][0]);
                    if (two) { ldsm4(Ah[1], abase[bufi][0][1]); ldsm4(Al[1], abase[bufi][1][1]); }
                    const uint32_t wbc = sbase + (uint32_t)(c*12288);
#pragma unroll
                    for (int g = 0; g < 3; g++) {
                        uint32_t Bh[4], Bl[4];
                        ldsm4(Bh, wbc + wboff[0][g]);
                        ldsm4(Bl, wbc + wboff[1][g]);
#pragma unroll
                        for (int j = 0; j < 2; j++) {
                            mma16816(acc[g][0][j], Ah[0], &Bh[j*2]);
                            mma16816(acc[g][0][j], Ah[0], &Bl[j*2]);
                            mma16816(acc[g][0][j], Al[0], &Bh[j*2]);
                        }
                        if (two) {
#pragma unroll
                            for (int j = 0; j < 2; j++) {
                                mma16816(acc[g][1][j], Ah[1], &Bh[j*2]);
                                mma16816(acc[g][1][j], Ah[1], &Bl[j*2]);
                                mma16816(acc[g][1][j], Al[1], &Bh[j*2]);
                            }
                        }
                    }
                }
            }
            // ---- epilogue ----
            __nv_bfloat16* Hhi_n = g_hhi[gru][par^1];
            __nv_bfloat16* Hlo_n = g_hlo[gru][par^1];
            const size_t offk = (size_t)32*(63*step - (step*(step-1))/2);
#pragma unroll
            for (int i = 0; i < 2; i++) {
                if (2*wm + i >= ng) continue;
#pragma unroll
                for (int half = 0; half < 2; half++) {
                    int grow = rowbase + wm*32 + i*16 + g8 + half*8;
                    int gxrow = grow - step*32;
                    const float* gxr = gx + (size_t)gxrow*(3*H_);
                    size_t prow = offk + gxrow;
                    float row_part = 0.f;
#pragma unroll
                    for (int j = 0; j < 2; j++) {
                        int cc = cb*64 + wn*16 + j*8 + t2;
                        float2 gx_r = *(const float2*)&gxr[cc];
                        float2 gx_z = *(const float2*)&gxr[H_ + cc];
                        float2 gx_n = *(const float2*)&gxr[2*H_ + cc];
                        float2 bh_r = *(const float2*)&bhh[cc];
                        float2 bh_z = *(const float2*)&bhh[H_ + cc];
                        float2 bh_n = *(const float2*)&bhh[2*H_ + cc];
                        __nv_bfloat162 ho_hi = *(const __nv_bfloat162*)&Hhi[(size_t)grow*H_ + cc];
                        __nv_bfloat162 ho_lo = *(const __nv_bfloat162*)&Hlo[(size_t)grow*H_ + cc];
                        float hn2[2];
#pragma unroll
                        for (int u = 0; u < 2; u++) {
                            int ai = half*2 + u;
                            float rp = acc[0][i][j][ai] + (u ? bh_r.y : bh_r.x) + (u ? gx_r.y : gx_r.x);
                            float zp = acc[1][i][j][ai] + (u ? bh_z.y : bh_z.x) + (u ? gx_z.y : gx_z.x);
                            float np = acc[2][i][j][ai] + (u ? bh_n.y : bh_n.x);
                            float r = 1.f/(1.f + expf(-rp));
                            float z = 1.f/(1.f + expf(-zp));
                            float n = tanhf((u ? gx_n.y : gx_n.x) + r*np);
                            float hold = __bfloat162float(u ? ho_hi.y : ho_hi.x)
                                       + __bfloat162float(u ? ho_lo.y : ho_lo.x);
                            hn2[u] = (1.f - z)*n + z*hold;
                        }
                        __nv_bfloat162 hi2, lo2;
                        hi2.x = __float2bfloat16(hn2[0]); hi2.y = __float2bfloat16(hn2[1]);
                        lo2.x = __float2bfloat16(hn2[0] - __bfloat162float(hi2.x));
                        lo2.y = __float2bfloat16(hn2[1] - __bfloat162float(hi2.y));
                        *(__nv_bfloat162*)&Hhi_n[(size_t)grow*H_ + cc] = hi2;
                        *(__nv_bfloat162*)&Hlo_n[(size_t)grow*H_ + cc] = lo2;
                        if (gru == 0) {
                            float2 aw = *(const float2*)&alpha_w[cc];
                            row_part += 0.5f*hn2[0]*aw.x + 0.5f*hn2[1]*aw.y;
                        } else {
                            float f0 = 0.5f*hn2[0], f1 = 0.5f*hn2[1];
                            __nv_bfloat162 fh, fl;
                            fh.x = __float2bfloat16(f0); fh.y = __float2bfloat16(f1);
                            fl.x = __float2bfloat16(f0 - __bfloat162float(fh.x));
                            fl.y = __float2bfloat16(f1 - __bfloat162float(fh.y));
                            *(__nv_bfloat162*)&g_fbhi[prow*H_ + cc] = fh;
                            *(__nv_bfloat162*)&g_fblo[prow*H_ + cc] = fl;
                        }
                    }
                    if (gru == 0) {
                        row_part += __shfl_xor_sync(0xffffffffu, row_part, 1);
                        row_part += __shfl_xor_sync(0xffffffffu, row_part, 2);
                        if ((lane & 3) == 0)
                            g_prep[prow*16 + cb*4 + wn] = row_part;
                    }
                }
            }
        }
        // ---- per-gru grid barrier (72 CTAs each) ----
        __syncthreads();
        if (tid == 0) {
            __threadfence();
            atomicAdd(mybar, 1u);
            const unsigned target = 72u*(unsigned)(step+1);
            unsigned v;
            do {
                asm volatile("ld.acquire.gpu.u32 %0, [%1];" : "=r"(v) : "l"(mybar));
            } while (v < target);
        }
        __syncthreads();
    }
}

// ------------------------- mma dense GEMM (M x 256, K=256) ------------------
__global__ void __launch_bounds__(512, 1)
dense_mma(const __nv_bfloat16* __restrict__ Ahi, const __nv_bfloat16* __restrict__ Alo,
          const __nv_bfloat16* __restrict__ Bthi, const __nv_bfloat16* __restrict__ Btlo,
          const float* __restrict__ bias, int act, float* __restrict__ outf,
          __nv_bfloat16* __restrict__ Phi, __nv_bfloat16* __restrict__ Plo) {
    extern __shared__ __align__(16) unsigned char smem[];
    const int tid = threadIdx.x, lane = tid & 31, wid = tid >> 5;
    const int wm = wid & 3, wn = wid >> 2;
    const int cb = blockIdx.y;
    const int rowbase = blockIdx.x * 128;
    const uint32_t sbase = smem_u32(smem);

    float acc[2][4][4] = {};

    const int a_r = lane & 15, a_c16 = ((lane >> 4) & 1) * 16;
    const int b_r = (lane & 7) + ((lane >> 4) & 1) * 8, b_c16 = (lane & 8) * 2;
    uint32_t aoff[3][2][2], boff[3][2][2];
#pragma unroll
    for (int bf = 0; bf < 3; bf++)
#pragma unroll
    for (int p = 0; p < 2; p++) {
#pragma unroll
        for (int i = 0; i < 2; i++)
            aoff[bf][p][i] = sbase + bf*DCHUNK + p*6144u
                           + (uint32_t)((wm*32 + i*16 + a_r)*48 + a_c16);
#pragma unroll
        for (int h2 = 0; h2 < 2; h2++)
            boff[bf][p][h2] = sbase + bf*DCHUNK + 12288u + p*6144u
                           + (uint32_t)((wn*32 + h2*16 + b_r)*48 + b_c16);
    }

    const int st_q = tid & 1, st_r = (tid >> 1) & 127, st_p = tid >> 8;
    const uint32_t stA = sbase + st_p*6144u + (uint32_t)(st_r*48 + st_q*16);
    const uint32_t stB = stA + 12288u;
    const __nv_bfloat16* srcA = (st_p ? Alo : Ahi) + (size_t)(rowbase + st_r)*256 + st_q*8;
    const __nv_bfloat16* srcB = (st_p ? Btlo : Bthi) + (size_t)(cb*128 + st_r)*256 + st_q*8;

    CP_ASYNC16(stA, srcA); CP_ASYNC16(stB, srcB); CP_COMMIT();
    CP_ASYNC16(stA + DCHUNK, srcA + 16); CP_ASYNC16(stB + DCHUNK, srcB + 16); CP_COMMIT();

    int bufi = 0;
#pragma unroll 1
    for (int c = 0; c < 16; c++) {
        if (c < 15) { CP_WAIT1(); } else { CP_WAIT0(); }
        __syncthreads();
        if (c < 14) {
            int nb = bufi + 2; if (nb >= 3) nb -= 3;
            CP_ASYNC16(stA + (uint32_t)(nb*DCHUNK), srcA + (c+2)*16);
            CP_ASYNC16(stB + (uint32_t)(nb*DCHUNK), srcB + (c+2)*16);
            CP_COMMIT();
        }
        uint32_t Ah[2][4], Al[2][4], Bh[8], Bl[8];
        ldsm4(Ah[0], aoff[bufi][0][0]); ldsm4(Ah[1], aoff[bufi][0][1]);
        ldsm4(Al[0], aoff[bufi][1][0]); ldsm4(Al[1], aoff[bufi][1][1]);
        ldsm4(Bh,   boff[bufi][0][0]); ldsm4(Bh+4, boff[bufi][0][1]);
        ldsm4(Bl,   boff[bufi][1][0]); ldsm4(Bl+4, boff[bufi][1][1]);
#pragma unroll
        for (int i = 0; i < 2; i++)
#pragma unroll
        for (int j = 0; j < 4; j++) {
            mma16816(acc[i][j], Ah[i], &Bh[j*2]);
            mma16816(acc[i][j], Ah[i], &Bl[j*2]);
            mma16816(acc[i][j], Al[i], &Bh[j*2]);
        }
        bufi++; if (bufi == 3) bufi = 0;
    }

    const int g8 = lane >> 2, t2 = (lane & 3)*2;
#pragma unroll
    for (int i = 0; i < 2; i++)
#pragma unroll
    for (int half = 0; half < 2; half++) {
        int grow = rowbase + wm*32 + i*16 + g8 + half*8;
#pragma unroll
        for (int j = 0; j < 4; j++) {
            int cc = cb*128 + wn*32 + j*8 + t2;
            float v0 = acc[i][j][half*2 + 0];
            float v1 = acc[i][j][half*2 + 1];
            if (bias) { v0 += bias[cc]; v1 += bias[cc+1]; }
            if (act == 1) { v0 = tanhf(v0); v1 = tanhf(v1); }
            float2 f2; f2.x = v0; f2.y = v1;
            *(float2*)&outf[(size_t)grow*E_ + cc] = f2;
            if (Phi) {
                __nv_bfloat162 hi2, lo2;
                hi2.x = __float2bfloat16(v0); hi2.y = __float2bfloat16(v1);
                lo2.x = __float2bfloat16(v0 - __bfloat162float(hi2.x));
                lo2.y = __float2bfloat16(v1 - __bfloat162float(hi2.y));
                *(__nv_bfloat162*)&Phi[(size_t)grow*E_ + cc] = hi2;
                *(__nv_bfloat162*)&Plo[(size_t)grow*E_ + cc] = lo2;
            }
        }
    }
}

// ------------------------- alpha (pre-partial sum + softmax) ----------------
__global__ void alpha_kernel(const float* __restrict__ alpha_b) {
    int gw = (blockIdx.x*blockDim.x + threadIdx.x) >> 5;
    int lane = threadIdx.x & 31;
    if (gw >= PB_) return;
    int p = gw >> 5, b = gw & 31;
    float ab = alpha_b[0];
    float v0 = -1e30f, v1 = -1e30f;
    {
        int t = lane;
        if (t <= p) {
            int kk = p - t;
            int offk = 32*(63*kk - (kk*(kk-1))/2);
            size_t prow = (size_t)offk + t*32 + b;
            const float4* qq = (const float4*)&g_prep[prow*16];
            float4 s0 = qq[0], s1 = qq[1], s2 = qq[2], s3 = qq[3];
            v0 = (s0.x+s0.y+s0.z+s0.w) + (s1.x+s1.y+s1.z+s1.w)
               + (s2.x+s2.y+s2.z+s2.w) + (s3.x+s3.y+s3.z+s3.w) + ab;
        }
    }
    {
        int t = lane + 32;
        if (t <= p) {
            int kk = p - t;
            int offk = 32*(63*kk - (kk*(kk-1))/2);
            size_t prow = (size_t)offk + t*32 + b;
            const float4* qq = (const float4*)&g_prep[prow*16];
            float4 s0 = qq[0], s1 = qq[1], s2 = qq[2], s3 = qq[3];
            v1 = (s0.x+s0.y+s0.z+s0.w) + (s1.x+s1.y+s1.z+s1.w)
               + (s2.x+s2.y+s2.z+s2.w) + (s3.x+s3.y+s3.z+s3.w) + ab;
        }
    }
    float m = fmaxf(v0, v1);
#pragma unroll
    for (int o=16;o;o>>=1) m = fmaxf(m, __shfl_xor_sync(0xffffffffu, m, o));
    float e0 = (lane      <= p) ? expf(v0-m) : 0.f;
    float e1 = (lane + 32 <= p) ? expf(v1-m) : 0.f;
    float s = e0 + e1;
#pragma unroll
    for (int o=16;o;o>>=1) s += __shfl_xor_sync(0xffffffffu, s, o);
    float inv = 1.f/s;
    g_alpha[(p*T_+lane   )*B_+b] = e0*inv;
    g_alpha[(p*T_+lane+32)*B_+b] = e1*inv;
}

__global__ void reduce_kernel(const float* __restrict__ x,
                              const float* __restrict__ out_w,
                              const float* __restrict__ out_b,
                              float* __restrict__ out) {
    int pb = blockIdx.x;
    int p = 62 - (pb >> 5);        // largest prefixes first (tail balance)
    int b = pb & 31;
    int e = threadIdx.x;
    float cc = 0.f, gg = 0.f;
    for (int t = 0; t <= p; t++) {
        float a = g_alpha[(p*T_+t)*B_+b];
        int kk = p - t;
        int offk = 32*(63*kk - (kk*(kk-1))/2);
        size_t prow = (size_t)offk + t*32 + b;
        cc += a * g_beta [prow*E_ + e] * g_emb[((size_t)(t*B_+b))*E_ + e];
        gg += a * g_ebeta[prow*E_ + e] * x[((size_t)b*T_ + t)*E_ + e];
    }
    out[B_*P_ + ((size_t)(b*P_+p))*E_ + e] = gg / (float)(p+1);
    __shared__ float red[256];
    red[e] = cc * out_w[e];
    __syncthreads();
    for (int s2=128; s2; s2>>=1) { if (e < s2) red[e] += red[e+s2]; __syncthreads(); }
    if (e == 0) out[b*P_ + p] = red[0] + out_b[0];
}

// ------------------------- launch -------------------------------------------
extern "C" void kernel_launch(void* const* d_in, const int* in_sizes, int n_in,
                              void* d_out, int out_size) {
    (void)in_sizes; (void)n_in; (void)out_size;
    const float* x       = (const float*)d_in[0];
    const float* emb_w   = (const float*)d_in[1];
    const float* emb_b   = (const float*)d_in[2];
    const float* a_wih   = (const float*)d_in[3];
    const float* a_whh   = (const float*)d_in[4];
    const float* a_bih   = (const float*)d_in[5];
    const float* a_bhh   = (const float*)d_in[6];
    const float* b_wih   = (const float*)d_in[7];
    const float* b_whh   = (const float*)d_in[8];
    const float* b_bih   = (const float*)d_in[9];
    const float* b_bhh   = (const float*)d_in[10];
    const float* alpha_w = (const float*)d_in[11];
    const float* alpha_b = (const float*)d_in[12];
    const float* beta_w  = (const float*)d_in[13];
    const float* beta_b  = (const float*)d_in[14];
    const float* out_w   = (const float*)d_in[15];
    const float* out_b   = (const float*)d_in[16];
    float* out = (float*)d_out;

    cudaFuncSetAttribute(gru_persistent, cudaFuncAttributeMaxDynamicSharedMemorySize, SMEM_TOTAL_PERS);
    cudaFuncSetAttribute(dense_mma,      cudaFuncAttributeMaxDynamicSharedMemorySize, SMEM_TOTAL_DENSE);

    float *p_emb=0, *p_gxa=0, *p_gxb=0, *p_beta=0, *p_ebeta=0;
    __nv_bfloat16 *p_fbhi=0, *p_fblo=0, *p_bwhi=0, *p_bwlo=0;
    __nv_bfloat16 *p_mthi=0, *p_mtlo=0, *p_bhi=0, *p_blo=0;
    cudaGetSymbolAddress((void**)&p_emb,   g_emb);
    cudaGetSymbolAddress((void**)&p_gxa,   g_gxa);
    cudaGetSymbolAddress((void**)&p_gxb,   g_gxb);
    cudaGetSymbolAddress((void**)&p_beta,  g_beta);
    cudaGetSymbolAddress((void**)&p_ebeta, g_ebeta);
    cudaGetSymbolAddress((void**)&p_fbhi,  g_fbhi);
    cudaGetSymbolAddress((void**)&p_fblo,  g_fblo);
    cudaGetSymbolAddress((void**)&p_bwhi,  g_bwhi);
    cudaGetSymbolAddress((void**)&p_bwlo,  g_bwlo);
    cudaGetSymbolAddress((void**)&p_mthi,  g_mthi);
    cudaGetSymbolAddress((void**)&p_mtlo,  g_mtlo);
    cudaGetSymbolAddress((void**)&p_bhi,   g_betahi);
    cudaGetSymbolAddress((void**)&p_blo,   g_betalo);

    zero_planes_kernel<<<(2*2*PB_*H_/2 + 255)/256, 256>>>();
    prep_w_kernel<<<(2*768*256)/256, 256>>>(a_whh, b_whh);
    prep_bw_kernel<<<256, 256>>>(beta_w);
    prep_mt_kernel<<<256, 256>>>(emb_w, out_w);

    sgemm128<<<dim3((T_*B_)/128, E_/128), 256>>>(x, emb_w, emb_b, p_emb, E_, 0, 1);
    sgemm128_gx<<<dim3((T_*B_)/128, 12), 256>>>(p_emb, a_wih, a_bih, p_gxa,
                                                b_wih, b_bih, p_gxb);

    gru_persistent<<<NCTA_PERS, 512, SMEM_TOTAL_PERS>>>(a_bhh, b_bhh, alpha_w);

    alpha_kernel<<<(PB_*32 + 255)/256, 256>>>(alpha_b);

    dense_mma<<<dim3(NPACK_/128, 2), 512, SMEM_TOTAL_DENSE>>>(
        p_fbhi, p_fblo, p_bwhi, p_bwlo, beta_b, 1, p_beta, p_bhi, p_blo);
    dense_mma<<<dim3(NPACK_/128, 2), 512, SMEM_TOTAL_DENSE>>>(
        p_bhi, p_blo, p_mthi, p_mtlo, (const float*)0, 0, p_ebeta,
        (__nv_bfloat16*)0, (__nv_bfloat16*)0);

    reduce_kernel<<<PB_, 256>>>(x, out_w, out_b, out);
}